// round 15
// baseline (speedup 1.0000x reference)
#include <cuda_runtime.h>
#include <cuda_bf16.h>
#include <cstdint>

#define BB 4
#define TT 2048
#define DD 1024
#define HH 16
#define DKK 64
#define DVV 128
#define KK 1024
#define VV 2048
#define MM 8192

typedef __nv_bfloat16 bf16;

// ---------------- scratch (device globals; no allocation) ----------------
__device__ float g_r [(size_t)MM*KK];
__device__ float g_k [(size_t)MM*KK];
__device__ float g_w [(size_t)MM*KK];
__device__ float g_xw[(size_t)MM*DD];
__device__ float g_v [(size_t)MM*VV];
__device__ float g_g [(size_t)MM*VV];
__device__ float g_o [(size_t)MM*VV];
__device__ float g_h1[(size_t)MM*32];
__device__ float g_h2[(size_t)MM*32];

__device__ bf16 g_xh[4][(size_t)MM*DD];   // modulated x planes (r,k,v,g) hi
__device__ bf16 g_xl[4][(size_t)MM*DD];   // lo
__device__ bf16 g_oh[(size_t)MM*VV], g_ol[(size_t)MM*VV];
__device__ bf16 g_wrh[(size_t)KK*DD], g_wrl[(size_t)KK*DD];
__device__ bf16 g_wkh[(size_t)KK*DD], g_wkl[(size_t)KK*DD];
__device__ bf16 g_wvh[(size_t)VV*DD], g_wvl[(size_t)VV*DD];
__device__ bf16 g_wgh[(size_t)VV*DD], g_wgl[(size_t)VV*DD];
__device__ bf16 g_woh[(size_t)DD*VV], g_wol[(size_t)DD*VV];

// ---------------- helpers ----------------
__device__ __forceinline__ uint32_t smem_u32(const void* p){
    uint32_t a;
    asm("{ .reg .u64 t; cvta.to.shared.u64 t, %1; cvt.u32.u64 %0, t; }" : "=r"(a) : "l"(p));
    return a;
}
__device__ __forceinline__ void split_bf16(float a, unsigned short& h, unsigned short& l){
    bf16 bh = __float2bfloat16(a);
    bf16 bl = __float2bfloat16(a - __bfloat162float(bh));
    h = *(unsigned short*)&bh; l = *(unsigned short*)&bl;
}

#define CP_ASYNC16(dst, src) \
    asm volatile("cp.async.cg.shared.global [%0], [%1], 16;" :: "r"(dst), "l"(src))
#define CP_COMMIT() asm volatile("cp.async.commit_group;")
#define CP_WAIT1()  asm volatile("cp.async.wait_group 1;" ::: "memory")

#define LDMX4(r0,r1,r2,r3,a) \
    asm volatile("ldmatrix.sync.aligned.m8n8.x4.shared.b16 {%0,%1,%2,%3}, [%4];" \
        : "=r"(r0), "=r"(r1), "=r"(r2), "=r"(r3) : "r"(a))

#define MMA16816(c0,c1,c2,c3,a0,a1,a2,a3,b0,b1) \
    asm volatile("mma.sync.aligned.m16n8k16.row.col.f32.bf16.bf16.f32 " \
        "{%0,%1,%2,%3}, {%4,%5,%6,%7}, {%8,%9}, {%0,%1,%2,%3};" \
        : "+f"(c0), "+f"(c1), "+f"(c2), "+f"(c3) \
        : "r"(a0), "r"(a1), "r"(a2), "r"(a3), "r"(b0), "r"(b1))

// smem tile layout per plane: [128 rows][32 bf16] = 64B rows, XOR swizzle
__device__ __forceinline__ uint32_t swz(int row, int seg){
    return (uint32_t)(row*64 + ((seg ^ ((row>>1)&3))<<4));
}

// ---------------- prep: modulated x -> 4 x (hi,lo) bf16 planes ----------------
__global__ __launch_bounds__(256)
void prep_x(const float* __restrict__ x,
            const float* __restrict__ mur, const float* __restrict__ muk,
            const float* __restrict__ muv, const float* __restrict__ mug)
{
    const int i4 = blockIdx.x * 256 + threadIdx.x;
    const int row = i4 / (DD/4), c4 = i4 % (DD/4);
    const float4 xv = *(const float4*)(x + (size_t)row*DD + c4*4);
    float4 pv;
    if ((row & (TT-1)) == 0) pv = make_float4(0.f,0.f,0.f,0.f);
    else pv = *(const float4*)(x + (size_t)(row-1)*DD + c4*4);
    const float xb[4] = {xv.x, xv.y, xv.z, xv.w};
    const float dx[4] = {pv.x-xv.x, pv.y-xv.y, pv.z-xv.z, pv.w-xv.w};
    const float* mus[4] = {mur, muk, muv, mug};
    const size_t off = (size_t)row*DD + c4*4;
#pragma unroll
    for (int v = 0; v < 4; v++) {
        const float4 m = *(const float4*)(mus[v] + c4*4);
        const float mm[4] = {m.x, m.y, m.z, m.w};
        unsigned short hs[4], ls[4];
#pragma unroll
        for (int j = 0; j < 4; j++) split_bf16(xb[j] + dx[j]*mm[j], hs[j], ls[j]);
        uint2 H, L;
        H.x = hs[0] | ((uint32_t)hs[1]<<16); H.y = hs[2] | ((uint32_t)hs[3]<<16);
        L.x = ls[0] | ((uint32_t)ls[1]<<16); L.y = ls[2] | ((uint32_t)ls[3]<<16);
        *(uint2*)(&g_xh[v][off]) = H;
        *(uint2*)(&g_xl[v][off]) = L;
    }
}

// ---------------- prep: W[Kd][N] -> Wt[N][Kd] hi/lo planes ----------------
__global__ void prep_wT(const float* __restrict__ W, bf16* __restrict__ Wh,
                        bf16* __restrict__ Wl, int Kd, int N)
{
    __shared__ float t[32][33];
    const int x = blockIdx.x*32 + threadIdx.x;   // N index
    const int y0 = blockIdx.y*32;                // Kd index
    for (int j = threadIdx.y; j < 32; j += 8)
        t[j][threadIdx.x] = W[(size_t)(y0+j)*N + x];
    __syncthreads();
    const int ox = y0 + threadIdx.x;
    const int oy0 = blockIdx.x*32;
    for (int j = threadIdx.y; j < 32; j += 8) {
        unsigned short h, l;
        split_bf16(t[threadIdx.x][j], h, l);
        Wh[(size_t)(oy0+j)*Kd + ox] = *(bf16*)&h;
        Wl[(size_t)(oy0+j)*Kd + ox] = *(bf16*)&l;
    }
}

// ---------------- HMMA split-bf16 GEMM: C[M,N] = A @ W ----------------
#define STAGES 3
#define PLANE_BYTES 8192            // 128 x 32 bf16
#define CHUNK_BYTES (4*PLANE_BYTES) // Ah, Al, Bh, Bl
#define MMA_SMEM (STAGES*CHUNK_BYTES)

__global__ __launch_bounds__(256, 2)
void gemm_mma(const bf16* __restrict__ Ah, const bf16* __restrict__ Al,
              const bf16* __restrict__ Bh, const bf16* __restrict__ Bl,
              float* __restrict__ C, int N, int Kd)
{
    extern __shared__ char smem[];
    const uint32_t sb = smem_u32(smem);
    const int tid = threadIdx.x, lane = tid & 31, wid = tid >> 5;
    const int m0 = blockIdx.y * 128, n0 = blockIdx.x * 128;
    const int wm = (wid & 3) * 32, wn = (wid >> 2) * 64;
    const int NC = Kd >> 5;

    const int r0_ = tid >> 2, s0_ = tid & 3;
    const uint32_t d0 = swz(r0_, s0_), d1 = swz(r0_ + 64, s0_);
    const size_t rowoff = (size_t)64 * Kd;
    const bf16* gp[4] = {
        Ah + (size_t)(m0 + r0_)*Kd + s0_*8,
        Al + (size_t)(m0 + r0_)*Kd + s0_*8,
        Bh + (size_t)(n0 + r0_)*Kd + s0_*8,
        Bl + (size_t)(n0 + r0_)*Kd + s0_*8 };

    uint32_t bufis = 0;
    auto issue = [&](int c){
        const uint32_t bb = sb + bufis * CHUNK_BYTES;
        if (++bufis == STAGES) bufis = 0;
        const int k0 = c * 32;
#pragma unroll
        for (int p = 0; p < 4; p++) {
            CP_ASYNC16(bb + p*PLANE_BYTES + d0, gp[p] + k0);
            CP_ASYNC16(bb + p*PLANE_BYTES + d1, gp[p] + rowoff + k0);
        }
        CP_COMMIT();
    };

    float acc[2][8][4];
#pragma unroll
    for (int mt = 0; mt < 2; mt++)
#pragma unroll
        for (int nt = 0; nt < 8; nt++)
#pragma unroll
            for (int q = 0; q < 4; q++) acc[mt][nt][q] = 0.f;

    issue(0); issue(1);

    const int a_row = wm + (lane & 15);
    const int a_s   = lane >> 4;
    const int b_row = wn + (lane & 7) + ((lane >> 4) << 3);
    const int b_s   = (lane >> 3) & 1;

    uint32_t bufc = 0;
    for (int c = 0; c < NC; c++) {
        CP_WAIT1();
        __syncthreads();
        if (c + 2 < NC) issue(c + 2);
        const uint32_t bb = sb + bufc * CHUNK_BYTES;
        if (++bufc == STAGES) bufc = 0;

#pragma unroll
        for (int s = 0; s < 2; s++) {
            uint32_t afh[2][4], afl[2][4];
#pragma unroll
            for (int mt = 0; mt < 2; mt++) {
                uint32_t ad = swz(a_row + mt*16, 2*s + a_s);
                LDMX4(afh[mt][0], afh[mt][1], afh[mt][2], afh[mt][3], bb + 0*PLANE_BYTES + ad);
                LDMX4(afl[mt][0], afl[mt][1], afl[mt][2], afl[mt][3], bb + 1*PLANE_BYTES + ad);
            }
#pragma unroll
            for (int nt2 = 0; nt2 < 4; nt2++) {
                uint32_t bd = swz(b_row + nt2*16, 2*s + b_s);
                uint32_t bh0,bh1,bh2,bh3, bl0,bl1,bl2,bl3;
                LDMX4(bh0, bh1, bh2, bh3, bb + 2*PLANE_BYTES + bd);
                LDMX4(bl0, bl1, bl2, bl3, bb + 3*PLANE_BYTES + bd);
#pragma unroll
                for (int mt = 0; mt < 2; mt++) {
                    float* a0 = acc[mt][2*nt2];
                    float* a1 = acc[mt][2*nt2+1];
                    MMA16816(a0[0],a0[1],a0[2],a0[3],
                             afh[mt][0],afh[mt][1],afh[mt][2],afh[mt][3], bh0,bh1);
                    MMA16816(a0[0],a0[1],a0[2],a0[3],
                             afl[mt][0],afl[mt][1],afl[mt][2],afl[mt][3], bh0,bh1);
                    MMA16816(a0[0],a0[1],a0[2],a0[3],
                             afh[mt][0],afh[mt][1],afh[mt][2],afh[mt][3], bl0,bl1);
                    MMA16816(a1[0],a1[1],a1[2],a1[3],
                             afh[mt][0],afh[mt][1],afh[mt][2],afh[mt][3], bh2,bh3);
                    MMA16816(a1[0],a1[1],a1[2],a1[3],
                             afl[mt][0],afl[mt][1],afl[mt][2],afl[mt][3], bh2,bh3);
                    MMA16816(a1[0],a1[1],a1[2],a1[3],
                             afh[mt][0],afh[mt][1],afh[mt][2],afh[mt][3], bl2,bl3);
                }
            }
        }
    }

#pragma unroll
    for (int mt = 0; mt < 2; mt++) {
        const int row = m0 + wm + mt*16 + (lane >> 2);
#pragma unroll
        for (int nt = 0; nt < 8; nt++) {
            const int col = n0 + wn + nt*8 + (lane & 3)*2;
            float2 v0 = make_float2(acc[mt][nt][0], acc[mt][nt][1]);
            float2 v1 = make_float2(acc[mt][nt][2], acc[mt][nt][3]);
            *(float2*)&C[(size_t)row*N + col]     = v0;
            *(float2*)&C[(size_t)(row+8)*N + col] = v1;
        }
    }
}

// ---------------- skinny GEMM: C[M,32] = tanh( Amod[M,Kd] @ W[Kd,32] ) ----------------
__global__ __launch_bounds__(256)
void gemm_skinny(const float* __restrict__ A, const float* __restrict__ W,
                 float* __restrict__ C, int Kd,
                 const float* __restrict__ mu, int amode)
{
    __shared__ float As[32][132];
    __shared__ float Bs[32][36];
    const int tid = threadIdx.x;
    const int colg = (tid & 7) * 4;
    const int rowg = (tid >> 3) * 4;
    const int m0 = blockIdx.x * 128;
    float acc[4][4];
#pragma unroll
    for (int i = 0; i < 4; i++)
#pragma unroll
        for (int j = 0; j < 4; j++) acc[i][j] = 0.f;

    for (int k0 = 0; k0 < Kd; k0 += 32) {
#pragma unroll
        for (int q = 0; q < 4; q++) {
            const int i = tid + 256*q;
            const int row = i >> 3, c4 = i & 7;
            const float* aptr = A + (size_t)(m0+row)*Kd + k0 + c4*4;
            float4 a = *(const float4*)aptr;
            if (amode) {
                float4 p;
                if (((m0+row) & (TT-1)) == 0) { p.x=p.y=p.z=p.w=0.f; }
                else p = *(const float4*)(aptr - Kd);
                float4 m4 = *(const float4*)(mu + k0 + c4*4);
                a.x += (p.x - a.x)*m4.x; a.y += (p.y - a.y)*m4.y;
                a.z += (p.z - a.z)*m4.z; a.w += (p.w - a.w)*m4.w;
            }
            As[c4*4+0][row] = a.x; As[c4*4+1][row] = a.y;
            As[c4*4+2][row] = a.z; As[c4*4+3][row] = a.w;
        }
        {
            const int krow = tid >> 3, c4 = tid & 7;
            float4 b = *(const float4*)(W + (size_t)(k0+krow)*32 + c4*4);
            Bs[krow][c4*4+0] = b.x; Bs[krow][c4*4+1] = b.y;
            Bs[krow][c4*4+2] = b.z; Bs[krow][c4*4+3] = b.w;
        }
        __syncthreads();
#pragma unroll
        for (int kk = 0; kk < 32; kk++) {
            float a[4], b[4];
            *(float4*)a = *(const float4*)&As[kk][rowg];
            *(float4*)b = *(const float4*)&Bs[kk][colg];
#pragma unroll
            for (int i = 0; i < 4; i++)
#pragma unroll
                for (int j = 0; j < 4; j++) acc[i][j] += a[i] * b[j];
        }
        __syncthreads();
    }
#pragma unroll
    for (int i = 0; i < 4; i++)
#pragma unroll
        for (int j = 0; j < 4; j++)
            C[(size_t)(m0+rowg+i)*32 + colg + j] = tanhf(acc[i][j]);
}

// ---------------- SIMT GEMM (wide LoRA: Kd=32) ----------------
#define GBM 128
#define GBN 128
#define GBK 8
template<int EPI>   // 2 = xw-combine, 3 = -exp(+bias)
__global__ __launch_bounds__(256)
void gemm_wide(const float* __restrict__ A, const float* __restrict__ B,
               float* __restrict__ C, int N, int Kd,
               const float* __restrict__ bias, const float* __restrict__ X)
{
    __shared__ float As[GBK][GBM];
    __shared__ float Bs[GBK][GBN + 4];
    const int tid = threadIdx.x;
    const int tx = tid & 15, ty = tid >> 4;
    const int rowA = tid >> 1, colA = (tid & 1) * 4;
    const int rowB = tid >> 5, colB = (tid & 31) * 4;
    const int gRowA = blockIdx.y * GBM + rowA;
    float acc[8][8];
#pragma unroll
    for (int i = 0; i < 8; i++)
#pragma unroll
        for (int j = 0; j < 8; j++) acc[i][j] = 0.f;
    const int gnB = blockIdx.x * GBN + colB;
    for (int k0 = 0; k0 < Kd; k0 += GBK) {
        float4 a = *(const float4*)(A + (size_t)gRowA * Kd + (k0 + colA));
        As[colA+0][rowA] = a.x; As[colA+1][rowA] = a.y;
        As[colA+2][rowA] = a.z; As[colA+3][rowA] = a.w;
        float4 b = *(const float4*)(B + (size_t)(k0 + rowB) * N + gnB);
        *(float4*)&Bs[rowB][colB] = b;
        __syncthreads();
#pragma unroll
        for (int kk = 0; kk < GBK; ++kk) {
            float ra[8], rb[8];
            *(float4*)&ra[0] = *(const float4*)&As[kk][ty*8];
            *(float4*)&ra[4] = *(const float4*)&As[kk][ty*8+4];
            *(float4*)&rb[0] = *(const float4*)&Bs[kk][tx*8];
            *(float4*)&rb[4] = *(const float4*)&Bs[kk][tx*8+4];
#pragma unroll
            for (int i = 0; i < 8; i++)
#pragma unroll
                for (int j = 0; j < 8; j++) acc[i][j] += ra[i] * rb[j];
        }
        __syncthreads();
    }
#pragma unroll
    for (int i = 0; i < 8; i++) {
        const int r = blockIdx.y * GBM + ty*8 + i;
        const bool rT0 = ((r & (TT - 1)) == 0);
#pragma unroll
        for (int j = 0; j < 8; j++) {
            const int col = blockIdx.x * GBN + tx*8 + j;
            const size_t cidx = (size_t)r * N + col;
            float vacc = acc[i][j];
            if (EPI == 2) {
                float lam = vacc + bias[col];
                float xv = X[cidx];
                float xp = rT0 ? 0.f : X[cidx - N];
                C[cidx] = xv + (xp - xv) * lam;
            } else C[cidx] = -expf(vacc + bias[col]);
        }
    }
}

// ---------------- recurrent scan v5: v-split-4 for 2 CTAs/SM ----------------
// 256 CTAs: (b,h,vq) with vq = v-quarter of 32. 256 threads: ko = tid>>5
// (8 k-octants of 8), vv = tid&31. State h[8]/thread. No shfl on the critical
// path (diagonal term rides the partial accumulators); spill-free depth-2
// prefetch via named scalars + x2-unrolled time loop (R12/R13 scheme).
// Most SMs hold 2 co-resident CTAs whose barriers interleave -> latency hidden.
__global__ __launch_bounds__(256)
void scan_kernel(const float* __restrict__ r, const float* __restrict__ k,
                 const float* __restrict__ v, const float* __restrict__ w,
                 const float* __restrict__ bonus, float* __restrict__ o)
{
    const int cta = blockIdx.x;
    const int bh = cta >> 2, vq = cta & 3;
    const int b = bh / HH, hh = bh % HH;
    const int tid = threadIdx.x;
    const int ko = tid >> 5, vv = tid & 31;
    const int kbase = ko * 8;

    __shared__ float s_r[DKK], s_k[DKK], s_ew[DKK], s_uk[DKK];
    __shared__ float s_v[32];
    __shared__ float s_part[8][32];

    const size_t rb = (size_t)(b * TT) * KK + hh * DKK;
    const size_t vb = (size_t)(b * TT) * VV + hh * DVV + vq * 32;

    float h[8];
#pragma unroll
    for (int i = 0; i < 8; i++) h[i] = 0.f;

    float u_ = 0.f;
    float P0r = 0.f, P0k = 0.f, P0w = 0.f, P0v = 0.f;
    float P1r = 0.f, P1k = 0.f, P1w = 0.f, P1v = 0.f;
    if (tid < 64) {
        u_ = bonus[hh * DKK + tid];
        P0r = r[rb + tid];      P0k = k[rb + tid];      P0w = w[rb + tid];
        P1r = r[rb + KK + tid]; P1k = k[rb + KK + tid]; P1w = w[rb + KK + tid];
    } else if (tid < 96) {
        P0v = v[vb + (tid - 64)];
        P1v = v[vb + VV + (tid - 64)];
    }

    auto step = [&](int t, float& Pr, float& Pk, float& Pw, float& Pv) {
        // publish step t (registers -> smem); no reduction here
        if (tid < 64) {
            float rv_ = Pr, kv_ = Pk;
            s_r[tid] = rv_; s_k[tid] = kv_;
            s_uk[tid] = u_ * kv_;
            s_ew[tid] = expf(Pw);
        } else if (tid < 96) {
            s_v[tid - 64] = Pv;
        }
        __syncthreads();

        // refill this slot with step t+2
        if (t + 2 < TT) {
            if (tid < 64) {
                const size_t ro2 = rb + (size_t)(t+2) * KK;
                Pr = r[ro2 + tid]; Pk = k[ro2 + tid]; Pw = w[ro2 + tid];
            } else if (tid < 96) {
                Pv = v[vb + (size_t)(t+2) * VV + (tid - 64)];
            }
        }

        // compute step t over this octant's 8 k-elems
        const float vvv = s_v[vv];
        float accp = 0.f, accd = 0.f;
#pragma unroll
        for (int i4 = 0; i4 < 2; i4++) {
            float4 r4 = *(const float4*)&s_r[kbase + i4*4];
            float4 k4 = *(const float4*)&s_k[kbase + i4*4];
            float4 e4 = *(const float4*)&s_ew[kbase + i4*4];
            float4 q4 = *(const float4*)&s_uk[kbase + i4*4];
            float* hp = &h[i4*4];
            accp += r4.x*hp[0]; accd += r4.x*q4.x; hp[0] = hp[0]*e4.x + k4.x*vvv;
            accp += r4.y*hp[1]; accd += r4.y*q4.y; hp[1] = hp[1]*e4.y + k4.y*vvv;
            accp += r4.z*hp[2]; accd += r4.z*q4.z; hp[2] = hp[2]*e4.z + k4.z*vvv;
            accp += r4.w*hp[3]; accd += r4.w*q4.w; hp[3] = hp[3]*e4.w + k4.w*vvv;
        }
        s_part[ko][vv] = accp + accd * vvv;
        __syncthreads();
        if (ko == 0) {
            float s = (accp + accd * vvv)
                + s_part[1][vv] + s_part[2][vv] + s_part[3][vv]
                + s_part[4][vv] + s_part[5][vv] + s_part[6][vv] + s_part[7][vv];
            o[vb + (size_t)t * VV + vv] = s;
        }
    };

    for (int t = 0; t < TT; t += 2) {
        step(t,     P0r, P0k, P0w, P0v);   // slot 0, refills t+2 (even)
        step(t + 1, P1r, P1k, P1w, P1v);   // slot 1, refills t+3 (odd)
    }
}

// ---------------- groupnorm + silu gate -> o hi/lo planes ----------------
__global__ __launch_bounds__(128)
void post_kernel(const float* __restrict__ o, const float* __restrict__ g,
                 const float* __restrict__ gnw)
{
    const int row = blockIdx.x;
    const int vv = threadIdx.x;
    const size_t idx = (size_t)row * DVV + vv;
    float val = o[idx];
    float sq = val * val;
#pragma unroll
    for (int off = 16; off > 0; off >>= 1)
        sq += __shfl_xor_sync(0xffffffff, sq, off);
    __shared__ float sw[4];
    if ((vv & 31) == 0) sw[vv >> 5] = sq;
    __syncthreads();
    float ms = (sw[0] + sw[1] + sw[2] + sw[3]) * (1.f / 128.f);
    float gv = g[idx];
    float sig = 1.f / (1.f + expf(-gv));
    float res = val * rsqrtf(ms + 1e-5f) * gnw[vv] * gv * sig;
    unsigned short h, l;
    split_bf16(res, h, l);
    g_oh[idx] = *(bf16*)&h;
    g_ol[idx] = *(bf16*)&l;
}

// ---------------- launch (serial, single stream — R6 order) ----------------
extern "C" void kernel_launch(void* const* d_in, const int* in_sizes, int n_in,
                              void* d_out, int out_size)
{
    const float* x        = (const float*)d_in[0];
    const float* W_r      = (const float*)d_in[1];
    const float* mu_r     = (const float*)d_in[2];
    const float* W_k      = (const float*)d_in[3];
    const float* mu_k     = (const float*)d_in[4];
    const float* W_v      = (const float*)d_in[5];
    const float* mu_v     = (const float*)d_in[6];
    const float* W_g      = (const float*)d_in[7];
    const float* mu_g     = (const float*)d_in[8];
    const float* dd_mu    = (const float*)d_in[9];
    const float* dd_W1    = (const float*)d_in[10];
    const float* dd_W2    = (const float*)d_in[11];
    const float* dd_lamda = (const float*)d_in[12];
    const float* w_W1     = (const float*)d_in[13];
    const float* w_W2     = (const float*)d_in[14];
    const float* w_lamda  = (const float*)d_in[15];
    const float* bonus    = (const float*)d_in[16];
    const float* W_o      = (const float*)d_in[17];
    const float* g_norm_w = (const float*)d_in[18];
    float* out = (float*)d_out;

    float *rP,*kP,*vP,*gP,*wP,*xwP,*h1P,*h2P,*oP;
    cudaGetSymbolAddress((void**)&rP,  g_r);
    cudaGetSymbolAddress((void**)&kP,  g_k);
    cudaGetSymbolAddress((void**)&vP,  g_v);
    cudaGetSymbolAddress((void**)&gP,  g_g);
    cudaGetSymbolAddress((void**)&wP,  g_w);
    cudaGetSymbolAddress((void**)&xwP, g_xw);
    cudaGetSymbolAddress((void**)&h1P, g_h1);
    cudaGetSymbolAddress((void**)&h2P, g_h2);
    cudaGetSymbolAddress((void**)&oP,  g_o);

    bf16 *xhP,*xlP,*ohP,*olP;
    bf16 *wrh,*wrl,*wkh,*wkl,*wvh,*wvl,*wgh,*wgl,*woh,*wol;
    cudaGetSymbolAddress((void**)&xhP, g_xh);
    cudaGetSymbolAddress((void**)&xlP, g_xl);
    cudaGetSymbolAddress((void**)&ohP, g_oh);
    cudaGetSymbolAddress((void**)&olP, g_ol);
    cudaGetSymbolAddress((void**)&wrh, g_wrh); cudaGetSymbolAddress((void**)&wrl, g_wrl);
    cudaGetSymbolAddress((void**)&wkh, g_wkh); cudaGetSymbolAddress((void**)&wkl, g_wkl);
    cudaGetSymbolAddress((void**)&wvh, g_wvh); cudaGetSymbolAddress((void**)&wvl, g_wvl);
    cudaGetSymbolAddress((void**)&wgh, g_wgh); cudaGetSymbolAddress((void**)&wgl, g_wgl);
    cudaGetSymbolAddress((void**)&woh, g_woh); cudaGetSymbolAddress((void**)&wol, g_wol);
    const size_t PL = (size_t)MM * DD;

    cudaFuncSetAttribute(gemm_mma, cudaFuncAttributeMaxDynamicSharedMemorySize, MMA_SMEM);

    const dim3 blk(256);
    // launches ordered so ncu (-s 5 -c 1) captures launch #6 = gemm_mma (same slot as before)
    prep_x<<<(MM*DD/4)/256, 256>>>(x, mu_r, mu_k, mu_v, mu_g);                      // 1
    prep_wT<<<dim3(KK/32, DD/32), dim3(32,8)>>>(W_r, wrh, wrl, DD, KK);             // 2
    prep_wT<<<dim3(VV/32, DD/32), dim3(32,8)>>>(W_v, wvh, wvl, DD, VV);             // 3
    gemm_mma<<<dim3(KK/128, MM/128), blk, MMA_SMEM>>>(xhP+0*PL, xlP+0*PL, wrh, wrl, rP, KK, DD); // 4
    prep_wT<<<dim3(KK/32, DD/32), dim3(32,8)>>>(W_k, wkh, wkl, DD, KK);             // 5
    gemm_mma<<<dim3(VV/128, MM/128), blk, MMA_SMEM>>>(xhP+2*PL, xlP+2*PL, wvh, wvl, vP, VV, DD); // 6 (profiled)
    gemm_mma<<<dim3(KK/128, MM/128), blk, MMA_SMEM>>>(xhP+1*PL, xlP+1*PL, wkh, wkl, kP, KK, DD); // 7
    prep_wT<<<dim3(VV/32, DD/32), dim3(32,8)>>>(W_g, wgh, wgl, DD, VV);             // 8
    gemm_mma<<<dim3(VV/128, MM/128), blk, MMA_SMEM>>>(xhP+3*PL, xlP+3*PL, wgh, wgl, gP, VV, DD); // 9
    prep_wT<<<dim3(DD/32, VV/32), dim3(32,8)>>>(W_o, woh, wol, VV, DD);             // 10

    // LoRA chains
    gemm_skinny<<<MM/128, blk>>>(x,   dd_W1, h1P, DD, dd_mu, 1);                    // 11
    gemm_wide<2><<<dim3(DD/GBN, MM/GBM), blk>>>(h1P, dd_W2, xwP, DD, 32, dd_lamda, x); // 12
    gemm_skinny<<<MM/128, blk>>>(xwP, w_W1,  h2P, DD, nullptr, 0);                  // 13
    gemm_wide<3><<<dim3(KK/GBN, MM/GBM), blk>>>(h2P, w_W2,  wP,  KK, 32, w_lamda, nullptr); // 14

    // recurrence (scan v5: v-split-4)
    scan_kernel<<<BB*HH*4, 256>>>(rP, kP, vP, wP, bonus, oP);                       // 15

    // groupnorm + silu gate -> o planes
    post_kernel<<<MM*HH, 128>>>(oP, gP, g_norm_w);                                  // 16

    // output projection
    gemm_mma<<<dim3(DD/128, MM/128), blk, MMA_SMEM>>>(ohP, olP, woh, wol, out, DD, VV); // 17
}

// round 16
// speedup vs baseline: 1.6481x; 1.6481x over previous
#include <cuda_runtime.h>
#include <cuda_bf16.h>
#include <cstdint>

#define BB 4
#define TT 2048
#define DD 1024
#define HH 16
#define DKK 64
#define DVV 128
#define KK 1024
#define VV 2048
#define MM 8192
#define NCT 8            // time chunks
#define CL  (TT/NCT)     // 256 steps per chunk

typedef __nv_bfloat16 bf16;

// ---------------- scratch (device globals; no allocation) ----------------
__device__ float g_r [(size_t)MM*KK];
__device__ float g_k [(size_t)MM*KK];
__device__ float g_w [(size_t)MM*KK];
__device__ float g_xw[(size_t)MM*DD];
__device__ float g_v [(size_t)MM*VV];
__device__ float g_g [(size_t)MM*VV];
__device__ float g_o [(size_t)MM*VV];
__device__ float g_h1[(size_t)MM*32];
__device__ float g_h2[(size_t)MM*32];

// chunked-scan state buffers: [bh(64)][chunk(8)][vhalf(2)][64k x 64v]
__device__ float g_hend[(size_t)64*NCT*2*4096];
__device__ float g_h0 [(size_t)64*NCT*2*4096];
__device__ float g_dc [(size_t)64*NCT*64];

__device__ bf16 g_xh[4][(size_t)MM*DD];   // modulated x planes (r,k,v,g) hi
__device__ bf16 g_xl[4][(size_t)MM*DD];   // lo
__device__ bf16 g_oh[(size_t)MM*VV], g_ol[(size_t)MM*VV];
__device__ bf16 g_wrh[(size_t)KK*DD], g_wrl[(size_t)KK*DD];
__device__ bf16 g_wkh[(size_t)KK*DD], g_wkl[(size_t)KK*DD];
__device__ bf16 g_wvh[(size_t)VV*DD], g_wvl[(size_t)VV*DD];
__device__ bf16 g_wgh[(size_t)VV*DD], g_wgl[(size_t)VV*DD];
__device__ bf16 g_woh[(size_t)DD*VV], g_wol[(size_t)DD*VV];

// ---------------- helpers ----------------
__device__ __forceinline__ uint32_t smem_u32(const void* p){
    uint32_t a;
    asm("{ .reg .u64 t; cvta.to.shared.u64 t, %1; cvt.u32.u64 %0, t; }" : "=r"(a) : "l"(p));
    return a;
}
__device__ __forceinline__ void split_bf16(float a, unsigned short& h, unsigned short& l){
    bf16 bh = __float2bfloat16(a);
    bf16 bl = __float2bfloat16(a - __bfloat162float(bh));
    h = *(unsigned short*)&bh; l = *(unsigned short*)&bl;
}

#define CP_ASYNC16(dst, src) \
    asm volatile("cp.async.cg.shared.global [%0], [%1], 16;" :: "r"(dst), "l"(src))
#define CP_COMMIT() asm volatile("cp.async.commit_group;")
#define CP_WAIT1()  asm volatile("cp.async.wait_group 1;" ::: "memory")

#define LDMX4(r0,r1,r2,r3,a) \
    asm volatile("ldmatrix.sync.aligned.m8n8.x4.shared.b16 {%0,%1,%2,%3}, [%4];" \
        : "=r"(r0), "=r"(r1), "=r"(r2), "=r"(r3) : "r"(a))

#define MMA16816(c0,c1,c2,c3,a0,a1,a2,a3,b0,b1) \
    asm volatile("mma.sync.aligned.m16n8k16.row.col.f32.bf16.bf16.f32 " \
        "{%0,%1,%2,%3}, {%4,%5,%6,%7}, {%8,%9}, {%0,%1,%2,%3};" \
        : "+f"(c0), "+f"(c1), "+f"(c2), "+f"(c3) \
        : "r"(a0), "r"(a1), "r"(a2), "r"(a3), "r"(b0), "r"(b1))

// smem tile layout per plane: [128 rows][32 bf16] = 64B rows, XOR swizzle
__device__ __forceinline__ uint32_t swz(int row, int seg){
    return (uint32_t)(row*64 + ((seg ^ ((row>>1)&3))<<4));
}

// ---------------- prep: modulated x -> 4 x (hi,lo) bf16 planes ----------------
__global__ __launch_bounds__(256)
void prep_x(const float* __restrict__ x,
            const float* __restrict__ mur, const float* __restrict__ muk,
            const float* __restrict__ muv, const float* __restrict__ mug)
{
    const int i4 = blockIdx.x * 256 + threadIdx.x;
    const int row = i4 / (DD/4), c4 = i4 % (DD/4);
    const float4 xv = *(const float4*)(x + (size_t)row*DD + c4*4);
    float4 pv;
    if ((row & (TT-1)) == 0) pv = make_float4(0.f,0.f,0.f,0.f);
    else pv = *(const float4*)(x + (size_t)(row-1)*DD + c4*4);
    const float xb[4] = {xv.x, xv.y, xv.z, xv.w};
    const float dx[4] = {pv.x-xv.x, pv.y-xv.y, pv.z-xv.z, pv.w-xv.w};
    const float* mus[4] = {mur, muk, muv, mug};
    const size_t off = (size_t)row*DD + c4*4;
#pragma unroll
    for (int v = 0; v < 4; v++) {
        const float4 m = *(const float4*)(mus[v] + c4*4);
        const float mm[4] = {m.x, m.y, m.z, m.w};
        unsigned short hs[4], ls[4];
#pragma unroll
        for (int j = 0; j < 4; j++) split_bf16(xb[j] + dx[j]*mm[j], hs[j], ls[j]);
        uint2 H, L;
        H.x = hs[0] | ((uint32_t)hs[1]<<16); H.y = hs[2] | ((uint32_t)hs[3]<<16);
        L.x = ls[0] | ((uint32_t)ls[1]<<16); L.y = ls[2] | ((uint32_t)ls[3]<<16);
        *(uint2*)(&g_xh[v][off]) = H;
        *(uint2*)(&g_xl[v][off]) = L;
    }
}

// ---------------- prep: W[Kd][N] -> Wt[N][Kd] hi/lo planes ----------------
__global__ void prep_wT(const float* __restrict__ W, bf16* __restrict__ Wh,
                        bf16* __restrict__ Wl, int Kd, int N)
{
    __shared__ float t[32][33];
    const int x = blockIdx.x*32 + threadIdx.x;   // N index
    const int y0 = blockIdx.y*32;                // Kd index
    for (int j = threadIdx.y; j < 32; j += 8)
        t[j][threadIdx.x] = W[(size_t)(y0+j)*N + x];
    __syncthreads();
    const int ox = y0 + threadIdx.x;
    const int oy0 = blockIdx.x*32;
    for (int j = threadIdx.y; j < 32; j += 8) {
        unsigned short h, l;
        split_bf16(t[threadIdx.x][j], h, l);
        Wh[(size_t)(oy0+j)*Kd + ox] = *(bf16*)&h;
        Wl[(size_t)(oy0+j)*Kd + ox] = *(bf16*)&l;
    }
}

// ---------------- HMMA split-bf16 GEMM: C[M,N] = A @ W ----------------
#define STAGES 3
#define PLANE_BYTES 8192            // 128 x 32 bf16
#define CHUNK_BYTES (4*PLANE_BYTES) // Ah, Al, Bh, Bl
#define MMA_SMEM (STAGES*CHUNK_BYTES)

__global__ __launch_bounds__(256, 2)
void gemm_mma(const bf16* __restrict__ Ah, const bf16* __restrict__ Al,
              const bf16* __restrict__ Bh, const bf16* __restrict__ Bl,
              float* __restrict__ C, int N, int Kd)
{
    extern __shared__ char smem[];
    const uint32_t sb = smem_u32(smem);
    const int tid = threadIdx.x, lane = tid & 31, wid = tid >> 5;
    const int m0 = blockIdx.y * 128, n0 = blockIdx.x * 128;
    const int wm = (wid & 3) * 32, wn = (wid >> 2) * 64;
    const int NC = Kd >> 5;

    const int r0_ = tid >> 2, s0_ = tid & 3;
    const uint32_t d0 = swz(r0_, s0_), d1 = swz(r0_ + 64, s0_);
    const size_t rowoff = (size_t)64 * Kd;
    const bf16* gp[4] = {
        Ah + (size_t)(m0 + r0_)*Kd + s0_*8,
        Al + (size_t)(m0 + r0_)*Kd + s0_*8,
        Bh + (size_t)(n0 + r0_)*Kd + s0_*8,
        Bl + (size_t)(n0 + r0_)*Kd + s0_*8 };

    uint32_t bufis = 0;
    auto issue = [&](int c){
        const uint32_t bb = sb + bufis * CHUNK_BYTES;
        if (++bufis == STAGES) bufis = 0;
        const int k0 = c * 32;
#pragma unroll
        for (int p = 0; p < 4; p++) {
            CP_ASYNC16(bb + p*PLANE_BYTES + d0, gp[p] + k0);
            CP_ASYNC16(bb + p*PLANE_BYTES + d1, gp[p] + rowoff + k0);
        }
        CP_COMMIT();
    };

    float acc[2][8][4];
#pragma unroll
    for (int mt = 0; mt < 2; mt++)
#pragma unroll
        for (int nt = 0; nt < 8; nt++)
#pragma unroll
            for (int q = 0; q < 4; q++) acc[mt][nt][q] = 0.f;

    issue(0); issue(1);

    const int a_row = wm + (lane & 15);
    const int a_s   = lane >> 4;
    const int b_row = wn + (lane & 7) + ((lane >> 4) << 3);
    const int b_s   = (lane >> 3) & 1;

    uint32_t bufc = 0;
    for (int c = 0; c < NC; c++) {
        CP_WAIT1();
        __syncthreads();
        if (c + 2 < NC) issue(c + 2);
        const uint32_t bb = sb + bufc * CHUNK_BYTES;
        if (++bufc == STAGES) bufc = 0;

#pragma unroll
        for (int s = 0; s < 2; s++) {
            uint32_t afh[2][4], afl[2][4];
#pragma unroll
            for (int mt = 0; mt < 2; mt++) {
                uint32_t ad = swz(a_row + mt*16, 2*s + a_s);
                LDMX4(afh[mt][0], afh[mt][1], afh[mt][2], afh[mt][3], bb + 0*PLANE_BYTES + ad);
                LDMX4(afl[mt][0], afl[mt][1], afl[mt][2], afl[mt][3], bb + 1*PLANE_BYTES + ad);
            }
#pragma unroll
            for (int nt2 = 0; nt2 < 4; nt2++) {
                uint32_t bd = swz(b_row + nt2*16, 2*s + b_s);
                uint32_t bh0,bh1,bh2,bh3, bl0,bl1,bl2,bl3;
                LDMX4(bh0, bh1, bh2, bh3, bb + 2*PLANE_BYTES + bd);
                LDMX4(bl0, bl1, bl2, bl3, bb + 3*PLANE_BYTES + bd);
#pragma unroll
                for (int mt = 0; mt < 2; mt++) {
                    float* a0 = acc[mt][2*nt2];
                    float* a1 = acc[mt][2*nt2+1];
                    MMA16816(a0[0],a0[1],a0[2],a0[3],
                             afh[mt][0],afh[mt][1],afh[mt][2],afh[mt][3], bh0,bh1);
                    MMA16816(a0[0],a0[1],a0[2],a0[3],
                             afl[mt][0],afl[mt][1],afl[mt][2],afl[mt][3], bh0,bh1);
                    MMA16816(a0[0],a0[1],a0[2],a0[3],
                             afh[mt][0],afh[mt][1],afh[mt][2],afh[mt][3], bl0,bl1);
                    MMA16816(a1[0],a1[1],a1[2],a1[3],
                             afh[mt][0],afh[mt][1],afh[mt][2],afh[mt][3], bh2,bh3);
                    MMA16816(a1[0],a1[1],a1[2],a1[3],
                             afl[mt][0],afl[mt][1],afl[mt][2],afl[mt][3], bh2,bh3);
                    MMA16816(a1[0],a1[1],a1[2],a1[3],
                             afh[mt][0],afh[mt][1],afh[mt][2],afh[mt][3], bl2,bl3);
                }
            }
        }
    }

#pragma unroll
    for (int mt = 0; mt < 2; mt++) {
        const int row = m0 + wm + mt*16 + (lane >> 2);
#pragma unroll
        for (int nt = 0; nt < 8; nt++) {
            const int col = n0 + wn + nt*8 + (lane & 3)*2;
            float2 v0 = make_float2(acc[mt][nt][0], acc[mt][nt][1]);
            float2 v1 = make_float2(acc[mt][nt][2], acc[mt][nt][3]);
            *(float2*)&C[(size_t)row*N + col]     = v0;
            *(float2*)&C[(size_t)(row+8)*N + col] = v1;
        }
    }
}

// ---------------- skinny GEMM: C[M,32] = tanh( Amod[M,Kd] @ W[Kd,32] ) ----------------
__global__ __launch_bounds__(256)
void gemm_skinny(const float* __restrict__ A, const float* __restrict__ W,
                 float* __restrict__ C, int Kd,
                 const float* __restrict__ mu, int amode)
{
    __shared__ float As[32][132];
    __shared__ float Bs[32][36];
    const int tid = threadIdx.x;
    const int colg = (tid & 7) * 4;
    const int rowg = (tid >> 3) * 4;
    const int m0 = blockIdx.x * 128;
    float acc[4][4];
#pragma unroll
    for (int i = 0; i < 4; i++)
#pragma unroll
        for (int j = 0; j < 4; j++) acc[i][j] = 0.f;

    for (int k0 = 0; k0 < Kd; k0 += 32) {
#pragma unroll
        for (int q = 0; q < 4; q++) {
            const int i = tid + 256*q;
            const int row = i >> 3, c4 = i & 7;
            const float* aptr = A + (size_t)(m0+row)*Kd + k0 + c4*4;
            float4 a = *(const float4*)aptr;
            if (amode) {
                float4 p;
                if (((m0+row) & (TT-1)) == 0) { p.x=p.y=p.z=p.w=0.f; }
                else p = *(const float4*)(aptr - Kd);
                float4 m4 = *(const float4*)(mu + k0 + c4*4);
                a.x += (p.x - a.x)*m4.x; a.y += (p.y - a.y)*m4.y;
                a.z += (p.z - a.z)*m4.z; a.w += (p.w - a.w)*m4.w;
            }
            As[c4*4+0][row] = a.x; As[c4*4+1][row] = a.y;
            As[c4*4+2][row] = a.z; As[c4*4+3][row] = a.w;
        }
        {
            const int krow = tid >> 3, c4 = tid & 7;
            float4 b = *(const float4*)(W + (size_t)(k0+krow)*32 + c4*4);
            Bs[krow][c4*4+0] = b.x; Bs[krow][c4*4+1] = b.y;
            Bs[krow][c4*4+2] = b.z; Bs[krow][c4*4+3] = b.w;
        }
        __syncthreads();
#pragma unroll
        for (int kk = 0; kk < 32; kk++) {
            float a[4], b[4];
            *(float4*)a = *(const float4*)&As[kk][rowg];
            *(float4*)b = *(const float4*)&Bs[kk][colg];
#pragma unroll
            for (int i = 0; i < 4; i++)
#pragma unroll
                for (int j = 0; j < 4; j++) acc[i][j] += a[i] * b[j];
        }
        __syncthreads();
    }
#pragma unroll
    for (int i = 0; i < 4; i++)
#pragma unroll
        for (int j = 0; j < 4; j++)
            C[(size_t)(m0+rowg+i)*32 + colg + j] = tanhf(acc[i][j]);
}

// ---------------- SIMT GEMM (wide LoRA: Kd=32) ----------------
#define GBM 128
#define GBN 128
#define GBK 8
template<int EPI>   // 2 = xw-combine, 3 = -exp(+bias)
__global__ __launch_bounds__(256)
void gemm_wide(const float* __restrict__ A, const float* __restrict__ B,
               float* __restrict__ C, int N, int Kd,
               const float* __restrict__ bias, const float* __restrict__ X)
{
    __shared__ float As[GBK][GBM];
    __shared__ float Bs[GBK][GBN + 4];
    const int tid = threadIdx.x;
    const int tx = tid & 15, ty = tid >> 4;
    const int rowA = tid >> 1, colA = (tid & 1) * 4;
    const int rowB = tid >> 5, colB = (tid & 31) * 4;
    const int gRowA = blockIdx.y * GBM + rowA;
    float acc[8][8];
#pragma unroll
    for (int i = 0; i < 8; i++)
#pragma unroll
        for (int j = 0; j < 8; j++) acc[i][j] = 0.f;
    const int gnB = blockIdx.x * GBN + colB;
    for (int k0 = 0; k0 < Kd; k0 += GBK) {
        float4 a = *(const float4*)(A + (size_t)gRowA * Kd + (k0 + colA));
        As[colA+0][rowA] = a.x; As[colA+1][rowA] = a.y;
        As[colA+2][rowA] = a.z; As[colA+3][rowA] = a.w;
        float4 b = *(const float4*)(B + (size_t)(k0 + rowB) * N + gnB);
        *(float4*)&Bs[rowB][colB] = b;
        __syncthreads();
#pragma unroll
        for (int kk = 0; kk < GBK; ++kk) {
            float ra[8], rb[8];
            *(float4*)&ra[0] = *(const float4*)&As[kk][ty*8];
            *(float4*)&ra[4] = *(const float4*)&As[kk][ty*8+4];
            *(float4*)&rb[0] = *(const float4*)&Bs[kk][tx*8];
            *(float4*)&rb[4] = *(const float4*)&Bs[kk][tx*8+4];
#pragma unroll
            for (int i = 0; i < 8; i++)
#pragma unroll
                for (int j = 0; j < 8; j++) acc[i][j] += ra[i] * rb[j];
        }
        __syncthreads();
    }
#pragma unroll
    for (int i = 0; i < 8; i++) {
        const int r = blockIdx.y * GBM + ty*8 + i;
        const bool rT0 = ((r & (TT - 1)) == 0);
#pragma unroll
        for (int j = 0; j < 8; j++) {
            const int col = blockIdx.x * GBN + tx*8 + j;
            const size_t cidx = (size_t)r * N + col;
            float vacc = acc[i][j];
            if (EPI == 2) {
                float lam = vacc + bias[col];
                float xv = X[cidx];
                float xp = rT0 ? 0.f : X[cidx - N];
                C[cidx] = xv + (xp - xv) * lam;
            } else C[cidx] = -expf(vacc + bias[col]);
        }
    }
}

// ---------------- chunked scan, pass 0: per-chunk decay exp(sum w) ----------------
__global__ __launch_bounds__(64)
void scan_dc(const float* __restrict__ w, float* __restrict__ dc)
{
    const int bh = blockIdx.x >> 3, ch = blockIdx.x & 7;
    const int b = bh / HH, hh = bh % HH;
    const int kk = threadIdx.x;
    const size_t rb = (size_t)(b * TT) * KK + hh * DKK + kk;
    float s = 0.f;
    for (int t = 0; t < CL; t++)
        s += w[rb + (size_t)(ch*CL + t) * KK];
    dc[(bh*NCT + ch)*64 + kk] = expf(s);
}

// ---------------- chunked scan, pass A: zero-init state evolution per chunk ----------------
// 1024 CTAs: (bh, chunk, vhalf). 256 threads: kq=tid>>6, vv=tid&63, h[16].
// Single barrier per step via compile-time double-buffered smem.
__global__ __launch_bounds__(256)
void scanA(const float* __restrict__ k, const float* __restrict__ v,
           const float* __restrict__ w, float* __restrict__ hend)
{
    const int cta = blockIdx.x;
    const int vhalf = cta & 1, ch = (cta >> 1) & 7, bh = cta >> 4;
    const int b = bh / HH, hh = bh % HH;
    const int tid = threadIdx.x;
    const int kq = tid >> 6, vv = tid & 63;
    const int kbase = kq * 16;

    __shared__ float s_k[2][64], s_ew[2][64], s_v[2][64];

    const size_t rb = (size_t)(b * TT) * KK + hh * DKK;
    const size_t vb = (size_t)(b * TT) * VV + hh * DVV + vhalf * 64;
    const int t0 = ch * CL, tend = t0 + CL;

    float h[16];
#pragma unroll
    for (int i = 0; i < 16; i++) h[i] = 0.f;

    float P0k = 0.f, P0w = 0.f, P0v = 0.f;
    float P1k = 0.f, P1w = 0.f, P1v = 0.f;
    if (tid < 64) {
        P0k = k[rb + (size_t)t0*KK + tid];     P0w = w[rb + (size_t)t0*KK + tid];
        P1k = k[rb + (size_t)(t0+1)*KK + tid]; P1w = w[rb + (size_t)(t0+1)*KK + tid];
    } else if (tid < 128) {
        P0v = v[vb + (size_t)t0*VV + (tid - 64)];
        P1v = v[vb + (size_t)(t0+1)*VV + (tid - 64)];
    }

    auto stepA = [&](int t, int B, float& Pk, float& Pw, float& Pv) {
        if (tid < 64) {
            s_k[B][tid] = Pk; s_ew[B][tid] = expf(Pw);
        } else if (tid < 128) {
            s_v[B][tid - 64] = Pv;
        }
        __syncthreads();
        if (t + 2 < tend) {
            if (tid < 64) {
                const size_t o2 = rb + (size_t)(t+2)*KK;
                Pk = k[o2 + tid]; Pw = w[o2 + tid];
            } else if (tid < 128) {
                Pv = v[vb + (size_t)(t+2)*VV + (tid - 64)];
            }
        }
        const float vvv = s_v[B][vv];
#pragma unroll
        for (int i4 = 0; i4 < 4; i4++) {
            float4 k4 = *(const float4*)&s_k[B][kbase + i4*4];
            float4 e4 = *(const float4*)&s_ew[B][kbase + i4*4];
            float* hp = &h[i4*4];
            hp[0] = hp[0]*e4.x + k4.x*vvv;
            hp[1] = hp[1]*e4.y + k4.y*vvv;
            hp[2] = hp[2]*e4.z + k4.z*vvv;
            hp[3] = hp[3]*e4.w + k4.w*vvv;
        }
    };

    for (int t = t0; t < tend; t += 2) {
        stepA(t,     0, P0k, P0w, P0v);
        stepA(t + 1, 1, P1k, P1w, P1v);
    }

    const size_t hb = ((size_t)(bh*NCT + ch)*2 + vhalf) * 4096;
#pragma unroll
    for (int i = 0; i < 16; i++)
        hend[hb + (size_t)(kbase + i)*64 + vv] = h[i];
}

// ---------------- chunked scan, combine: stitch chunk states sequentially ----------------
// 128 CTAs: (bh, vhalf). 256 threads x 16 elems each (4096 state elems).
__global__ __launch_bounds__(256)
void scan_combine(const float* __restrict__ hend, const float* __restrict__ dc,
                  float* __restrict__ h0)
{
    const int bh = blockIdx.x >> 1, vhalf = blockIdx.x & 1;
    const int tid = threadIdx.x;
    float H[16];
#pragma unroll
    for (int j = 0; j < 16; j++) H[j] = 0.f;
    for (int ch = 0; ch < NCT; ch++) {
        const size_t base = ((size_t)(bh*NCT + ch)*2 + vhalf) * 4096;
#pragma unroll
        for (int j = 0; j < 16; j++) {
            const int e = tid + j*256;
            h0[base + e] = H[j];
            H[j] = hend[base + e] + dc[(bh*NCT + ch)*64 + (e >> 6)] * H[j];
        }
    }
}

// ---------------- chunked scan, pass B: output with correct h0 (R13 v4 body) ----------------
// 1024 CTAs: (bh, chunk, vhalf). 256 threads: kq=tid>>6, vv=tid&63, h[16] from g_h0.
__global__ __launch_bounds__(256)
void scanB(const float* __restrict__ r, const float* __restrict__ k,
           const float* __restrict__ v, const float* __restrict__ w,
           const float* __restrict__ bonus, const float* __restrict__ h0,
           float* __restrict__ o)
{
    const int cta = blockIdx.x;
    const int vhalf = cta & 1, ch = (cta >> 1) & 7, bh = cta >> 4;
    const int b = bh / HH, hh = bh % HH;
    const int tid = threadIdx.x;
    const int kq = tid >> 6, vv = tid & 63;
    const int kbase = kq * 16;

    __shared__ float s_r[DKK], s_k[DKK], s_ew[DKK], s_uk[DKK];
    __shared__ float s_v[64];
    __shared__ float s_part[4][64];

    const size_t rb = (size_t)(b * TT) * KK + hh * DKK;
    const size_t vb = (size_t)(b * TT) * VV + hh * DVV + vhalf * 64;
    const int t0 = ch * CL, tend = t0 + CL;

    float h[16];
    {
        const size_t hb = ((size_t)(bh*NCT + ch)*2 + vhalf) * 4096;
#pragma unroll
        for (int i = 0; i < 16; i++)
            h[i] = h0[hb + (size_t)(kbase + i)*64 + vv];
    }

    float u_ = 0.f;
    float P0r = 0.f, P0k = 0.f, P0w = 0.f, P0v = 0.f;
    float P1r = 0.f, P1k = 0.f, P1w = 0.f, P1v = 0.f;
    if (tid < 64) {
        u_ = bonus[hh * DKK + tid];
        P0r = r[rb + (size_t)t0*KK + tid];     P0k = k[rb + (size_t)t0*KK + tid];     P0w = w[rb + (size_t)t0*KK + tid];
        P1r = r[rb + (size_t)(t0+1)*KK + tid]; P1k = k[rb + (size_t)(t0+1)*KK + tid]; P1w = w[rb + (size_t)(t0+1)*KK + tid];
    } else if (tid < 128) {
        P0v = v[vb + (size_t)t0*VV + (tid - 64)];
        P1v = v[vb + (size_t)(t0+1)*VV + (tid - 64)];
    }

    auto step = [&](int t, float& Pr, float& Pk, float& Pw, float& Pv) {
        if (tid < 64) {
            float rv_ = Pr, kv_ = Pk;
            s_r[tid] = rv_; s_k[tid] = kv_;
            s_uk[tid] = u_ * kv_;
            s_ew[tid] = expf(Pw);
        } else if (tid < 128) {
            s_v[tid - 64] = Pv;
        }
        __syncthreads();

        if (t + 2 < tend) {
            if (tid < 64) {
                const size_t ro2 = rb + (size_t)(t+2) * KK;
                Pr = r[ro2 + tid]; Pk = k[ro2 + tid]; Pw = w[ro2 + tid];
            } else if (tid < 128) {
                Pv = v[vb + (size_t)(t+2) * VV + (tid - 64)];
            }
        }

        const float vvv = s_v[vv];
        float accp = 0.f, accd = 0.f;
#pragma unroll
        for (int i4 = 0; i4 < 4; i4++) {
            float4 r4 = *(const float4*)&s_r[kbase + i4*4];
            float4 k4 = *(const float4*)&s_k[kbase + i4*4];
            float4 e4 = *(const float4*)&s_ew[kbase + i4*4];
            float4 q4 = *(const float4*)&s_uk[kbase + i4*4];
            float* hp = &h[i4*4];
            accp += r4.x*hp[0]; accd += r4.x*q4.x; hp[0] = hp[0]*e4.x + k4.x*vvv;
            accp += r4.y*hp[1]; accd += r4.y*q4.y; hp[1] = hp[1]*e4.y + k4.y*vvv;
            accp += r4.z*hp[2]; accd += r4.z*q4.z; hp[2] = hp[2]*e4.z + k4.z*vvv;
            accp += r4.w*hp[3]; accd += r4.w*q4.w; hp[3] = hp[3]*e4.w + k4.w*vvv;
        }
        s_part[kq][vv] = accp + accd * vvv;
        __syncthreads();
        if (kq == 0) {
            o[vb + (size_t)t * VV + vv] = (accp + accd * vvv)
                + s_part[1][vv] + s_part[2][vv] + s_part[3][vv];
        }
    };

    for (int t = t0; t < tend; t += 2) {
        step(t,     P0r, P0k, P0w, P0v);
        step(t + 1, P1r, P1k, P1w, P1v);
    }
}

// ---------------- groupnorm + silu gate -> o hi/lo planes ----------------
__global__ __launch_bounds__(128)
void post_kernel(const float* __restrict__ o, const float* __restrict__ g,
                 const float* __restrict__ gnw)
{
    const int row = blockIdx.x;
    const int vv = threadIdx.x;
    const size_t idx = (size_t)row * DVV + vv;
    float val = o[idx];
    float sq = val * val;
#pragma unroll
    for (int off = 16; off > 0; off >>= 1)
        sq += __shfl_xor_sync(0xffffffff, sq, off);
    __shared__ float sw[4];
    if ((vv & 31) == 0) sw[vv >> 5] = sq;
    __syncthreads();
    float ms = (sw[0] + sw[1] + sw[2] + sw[3]) * (1.f / 128.f);
    float gv = g[idx];
    float sig = 1.f / (1.f + expf(-gv));
    float res = val * rsqrtf(ms + 1e-5f) * gnw[vv] * gv * sig;
    unsigned short h, l;
    split_bf16(res, h, l);
    g_oh[idx] = *(bf16*)&h;
    g_ol[idx] = *(bf16*)&l;
}

// ---------------- launch (serial, single stream) ----------------
extern "C" void kernel_launch(void* const* d_in, const int* in_sizes, int n_in,
                              void* d_out, int out_size)
{
    const float* x        = (const float*)d_in[0];
    const float* W_r      = (const float*)d_in[1];
    const float* mu_r     = (const float*)d_in[2];
    const float* W_k      = (const float*)d_in[3];
    const float* mu_k     = (const float*)d_in[4];
    const float* W_v      = (const float*)d_in[5];
    const float* mu_v     = (const float*)d_in[6];
    const float* W_g      = (const float*)d_in[7];
    const float* mu_g     = (const float*)d_in[8];
    const float* dd_mu    = (const float*)d_in[9];
    const float* dd_W1    = (const float*)d_in[10];
    const float* dd_W2    = (const float*)d_in[11];
    const float* dd_lamda = (const float*)d_in[12];
    const float* w_W1     = (const float*)d_in[13];
    const float* w_W2     = (const float*)d_in[14];
    const float* w_lamda  = (const float*)d_in[15];
    const float* bonus    = (const float*)d_in[16];
    const float* W_o      = (const float*)d_in[17];
    const float* g_norm_w = (const float*)d_in[18];
    float* out = (float*)d_out;

    float *rP,*kP,*vP,*gP,*wP,*xwP,*h1P,*h2P,*oP;
    float *hendP,*h0P,*dcP;
    cudaGetSymbolAddress((void**)&rP,  g_r);
    cudaGetSymbolAddress((void**)&kP,  g_k);
    cudaGetSymbolAddress((void**)&vP,  g_v);
    cudaGetSymbolAddress((void**)&gP,  g_g);
    cudaGetSymbolAddress((void**)&wP,  g_w);
    cudaGetSymbolAddress((void**)&xwP, g_xw);
    cudaGetSymbolAddress((void**)&h1P, g_h1);
    cudaGetSymbolAddress((void**)&h2P, g_h2);
    cudaGetSymbolAddress((void**)&oP,  g_o);
    cudaGetSymbolAddress((void**)&hendP, g_hend);
    cudaGetSymbolAddress((void**)&h0P,   g_h0);
    cudaGetSymbolAddress((void**)&dcP,   g_dc);

    bf16 *xhP,*xlP,*ohP,*olP;
    bf16 *wrh,*wrl,*wkh,*wkl,*wvh,*wvl,*wgh,*wgl,*woh,*wol;
    cudaGetSymbolAddress((void**)&xhP, g_xh);
    cudaGetSymbolAddress((void**)&xlP, g_xl);
    cudaGetSymbolAddress((void**)&ohP, g_oh);
    cudaGetSymbolAddress((void**)&olP, g_ol);
    cudaGetSymbolAddress((void**)&wrh, g_wrh); cudaGetSymbolAddress((void**)&wrl, g_wrl);
    cudaGetSymbolAddress((void**)&wkh, g_wkh); cudaGetSymbolAddress((void**)&wkl, g_wkl);
    cudaGetSymbolAddress((void**)&wvh, g_wvh); cudaGetSymbolAddress((void**)&wvl, g_wvl);
    cudaGetSymbolAddress((void**)&wgh, g_wgh); cudaGetSymbolAddress((void**)&wgl, g_wgl);
    cudaGetSymbolAddress((void**)&woh, g_woh); cudaGetSymbolAddress((void**)&wol, g_wol);
    const size_t PL = (size_t)MM * DD;

    cudaFuncSetAttribute(gemm_mma, cudaFuncAttributeMaxDynamicSharedMemorySize, MMA_SMEM);

    const dim3 blk(256);
    // launches ordered so ncu (-s 5 -c 1) captures launch #6 = gemm_mma (same slot as before)
    prep_x<<<(MM*DD/4)/256, 256>>>(x, mu_r, mu_k, mu_v, mu_g);                      // 1
    prep_wT<<<dim3(KK/32, DD/32), dim3(32,8)>>>(W_r, wrh, wrl, DD, KK);             // 2
    prep_wT<<<dim3(VV/32, DD/32), dim3(32,8)>>>(W_v, wvh, wvl, DD, VV);             // 3
    gemm_mma<<<dim3(KK/128, MM/128), blk, MMA_SMEM>>>(xhP+0*PL, xlP+0*PL, wrh, wrl, rP, KK, DD); // 4
    prep_wT<<<dim3(KK/32, DD/32), dim3(32,8)>>>(W_k, wkh, wkl, DD, KK);             // 5
    gemm_mma<<<dim3(VV/128, MM/128), blk, MMA_SMEM>>>(xhP+2*PL, xlP+2*PL, wvh, wvl, vP, VV, DD); // 6 (profiled)
    gemm_mma<<<dim3(KK/128, MM/128), blk, MMA_SMEM>>>(xhP+1*PL, xlP+1*PL, wkh, wkl, kP, KK, DD); // 7
    prep_wT<<<dim3(VV/32, DD/32), dim3(32,8)>>>(W_g, wgh, wgl, DD, VV);             // 8
    gemm_mma<<<dim3(VV/128, MM/128), blk, MMA_SMEM>>>(xhP+3*PL, xlP+3*PL, wgh, wgl, gP, VV, DD); // 9
    prep_wT<<<dim3(DD/32, VV/32), dim3(32,8)>>>(W_o, woh, wol, VV, DD);             // 10

    // LoRA chains
    gemm_skinny<<<MM/128, blk>>>(x,   dd_W1, h1P, DD, dd_mu, 1);                    // 11
    gemm_wide<2><<<dim3(DD/GBN, MM/GBM), blk>>>(h1P, dd_W2, xwP, DD, 32, dd_lamda, x); // 12
    gemm_skinny<<<MM/128, blk>>>(xwP, w_W1,  h2P, DD, nullptr, 0);                  // 13
    gemm_wide<3><<<dim3(KK/GBN, MM/GBM), blk>>>(h2P, w_W2,  wP,  KK, 32, w_lamda, nullptr); // 14

    // chunked recurrence: decay, chunk evolution, stitch, output
    scan_dc<<<64*NCT, 64>>>(wP, dcP);                                               // 15
    scanA<<<64*NCT*2, 256>>>(kP, vP, wP, hendP);                                    // 16
    scan_combine<<<128, 256>>>(hendP, dcP, h0P);                                    // 17
    scanB<<<64*NCT*2, 256>>>(rP, kP, vP, wP, bonus, h0P, oP);                       // 18

    // groupnorm + silu gate -> o planes
    post_kernel<<<MM*HH, 128>>>(oP, gP, g_norm_w);                                  // 19

    // output projection
    gemm_mma<<<dim3(DD/128, MM/128), blk, MMA_SMEM>>>(ohP, olP, woh, wol, out, DD, VV); // 20
}